// round 2
// baseline (speedup 1.0000x reference)
#include <cuda_runtime.h>
#include <math.h>

// Problem constants
constexpr int B_  = 4;
constexpr int T_  = 1024;
constexpr int C_  = 768;
constexpr int NH_ = 12;
constexpr int HD_ = 64;
constexpr int C3_ = 3 * C_;          // 2304
constexpr int MR_ = B_ * T_;         // 4096 rows

// Scratch (static device globals — no allocation)
__device__ float g_qkv[(size_t)MR_ * C3_];    // [4096, 2304]
__device__ float g_attn[(size_t)MR_ * C_];    // [4096, 768]

// ---------------------------------------------------------------------------
// GEMM: C = A[M,K] @ B[K,N] + bias[N]
// 128x128 tile, BK=16, 256 threads, 8x8 per-thread micro-tile.
// ---------------------------------------------------------------------------
__global__ __launch_bounds__(256) void gemm_bias_kernel(
    const float* __restrict__ A, const float* __restrict__ Bm,
    const float* __restrict__ bias, float* __restrict__ C,
    int M, int N, int K)
{
    constexpr int BM = 128, BN = 128, BK = 16;
    __shared__ float As[BK][BM];   // stored transposed: As[k][m]
    __shared__ float Bs[BK][BN];

    const int tid = threadIdx.x;
    const int ty = tid >> 4;       // 0..15
    const int tx = tid & 15;       // 0..15
    const int m0 = blockIdx.y * BM;
    const int n0 = blockIdx.x * BN;
    const int ry = ty * 8;
    const int cx = tx * 8;

    float acc[8][8];
    #pragma unroll
    for (int i = 0; i < 8; i++)
        #pragma unroll
        for (int j = 0; j < 8; j++) acc[i][j] = 0.f;

    for (int k0 = 0; k0 < K; k0 += BK) {
        // Load A tile (BM x BK) -> As[k][m] (transposed)
        #pragma unroll
        for (int it = 0; it < 2; it++) {
            int li = tid + it * 256;           // 0..511
            int r  = li >> 2;                  // 0..127
            int c4 = li & 3;                   // 0..3
            float4 v = *(const float4*)&A[(size_t)(m0 + r) * K + k0 + c4 * 4];
            As[c4 * 4 + 0][r] = v.x;
            As[c4 * 4 + 1][r] = v.y;
            As[c4 * 4 + 2][r] = v.z;
            As[c4 * 4 + 3][r] = v.w;
        }
        // Load B tile (BK x BN)
        #pragma unroll
        for (int it = 0; it < 2; it++) {
            int li = tid + it * 256;           // 0..511
            int r  = li >> 5;                  // 0..15
            int c4 = li & 31;                  // 0..31
            *(float4*)&Bs[r][c4 * 4] =
                *(const float4*)&Bm[(size_t)(k0 + r) * N + n0 + c4 * 4];
        }
        __syncthreads();

        #pragma unroll
        for (int kk = 0; kk < BK; kk++) {
            float a[8], b[8];
            *(float4*)&a[0] = *(const float4*)&As[kk][ry];
            *(float4*)&a[4] = *(const float4*)&As[kk][ry + 4];
            *(float4*)&b[0] = *(const float4*)&Bs[kk][cx];
            *(float4*)&b[4] = *(const float4*)&Bs[kk][cx + 4];
            #pragma unroll
            for (int i = 0; i < 8; i++)
                #pragma unroll
                for (int j = 0; j < 8; j++)
                    acc[i][j] += a[i] * b[j];
        }
        __syncthreads();
    }

    float bv[8];
    *(float4*)&bv[0] = *(const float4*)&bias[n0 + cx];
    *(float4*)&bv[4] = *(const float4*)&bias[n0 + cx + 4];
    #pragma unroll
    for (int i = 0; i < 8; i++) {
        float4 o0 = make_float4(acc[i][0] + bv[0], acc[i][1] + bv[1],
                                acc[i][2] + bv[2], acc[i][3] + bv[3]);
        float4 o1 = make_float4(acc[i][4] + bv[4], acc[i][5] + bv[5],
                                acc[i][6] + bv[6], acc[i][7] + bv[7]);
        size_t row = (size_t)(m0 + ry + i) * N + n0 + cx;
        *(float4*)&C[row]     = o0;
        *(float4*)&C[row + 4] = o1;
    }
}

// ---------------------------------------------------------------------------
// Fused causal flash attention (fp32, online softmax).
// Grid: (T/64, NH, B). Block: 256 threads (16x16).
// q-tile = 64 rows, k-tile = 32 keys. Each thread owns 4 q-rows x (2 S-cols /
// 4 O-cols). Softmax stats in registers (16-lane shfl reductions).
// Reads q/k/v slices out of g_qkv, writes [B*T, C]-layout into g_attn.
// ---------------------------------------------------------------------------
__global__ __launch_bounds__(256) void attn_kernel(
    const float* __restrict__ qkv, float* __restrict__ outp)
{
    __shared__ float Qs[64][65];
    __shared__ float Ks[32][65];
    __shared__ float Vs[32][64];
    __shared__ float Ps[64][33];

    const int tid = threadIdx.x;
    const int ty = tid >> 4;     // 0..15 -> q rows 4*ty..4*ty+3
    const int tx = tid & 15;     // 0..15 -> S cols 2*tx..+1, O cols 4*tx..+3
    const int qt = blockIdx.x;
    const int h  = blockIdx.y;
    const int b  = blockIdx.z;
    const int q0 = qt * 64;
    const float scale = 0.125f;  // 1/sqrt(64)

    // Load Q tile [64 x 64]
    for (int i = tid; i < 64 * 16; i += 256) {
        int r  = i >> 4;
        int c4 = i & 15;
        float4 v = *(const float4*)&qkv[(size_t)(b * T_ + q0 + r) * C3_ + h * HD_ + c4 * 4];
        Qs[r][c4 * 4 + 0] = v.x;
        Qs[r][c4 * 4 + 1] = v.y;
        Qs[r][c4 * 4 + 2] = v.z;
        Qs[r][c4 * 4 + 3] = v.w;
    }

    float acc[4][4];
    float mi[4], li[4];
    #pragma unroll
    for (int i = 0; i < 4; i++) {
        mi[i] = -1e9f; li[i] = 0.f;
        #pragma unroll
        for (int c = 0; c < 4; c++) acc[i][c] = 0.f;
    }

    const int nkt = (q0 + 64) >> 5;   // causal: only k-tiles at/below diagonal
    for (int kt = 0; kt < nkt; kt++) {
        const int k0 = kt << 5;
        __syncthreads();   // protect Ks/Vs reuse (and first-iter Q load)
        // Load K,V tiles [32 x 64]
        for (int i = tid; i < 32 * 16; i += 256) {
            int r  = i >> 4;
            int c4 = i & 15;
            size_t base = (size_t)(b * T_ + k0 + r) * C3_ + h * HD_ + c4 * 4;
            float4 kv = *(const float4*)&qkv[base + C_];
            Ks[r][c4 * 4 + 0] = kv.x;
            Ks[r][c4 * 4 + 1] = kv.y;
            Ks[r][c4 * 4 + 2] = kv.z;
            Ks[r][c4 * 4 + 3] = kv.w;
            *(float4*)&Vs[r][c4 * 4] = *(const float4*)&qkv[base + 2 * C_];
        }
        __syncthreads();

        // S = scale * Q @ K^T  (4x2 per thread)
        float s[4][2] = {{0.f,0.f},{0.f,0.f},{0.f,0.f},{0.f,0.f}};
        #pragma unroll 8
        for (int d = 0; d < 64; d++) {
            float q0f = Qs[ty * 4 + 0][d];
            float q1f = Qs[ty * 4 + 1][d];
            float q2f = Qs[ty * 4 + 2][d];
            float q3f = Qs[ty * 4 + 3][d];
            float k0f = Ks[tx * 2 + 0][d];
            float k1f = Ks[tx * 2 + 1][d];
            s[0][0] += q0f * k0f;  s[0][1] += q0f * k1f;
            s[1][0] += q1f * k0f;  s[1][1] += q1f * k1f;
            s[2][0] += q2f * k0f;  s[2][1] += q2f * k1f;
            s[3][0] += q3f * k0f;  s[3][1] += q3f * k1f;
        }
        // scale + causal mask
        #pragma unroll
        for (int i = 0; i < 4; i++) {
            int qg = q0 + ty * 4 + i;
            #pragma unroll
            for (int j = 0; j < 2; j++) {
                int kg = k0 + tx * 2 + j;
                s[i][j] = (kg <= qg) ? s[i][j] * scale : -1e9f;
            }
        }
        // online softmax: per-row reduce across the 16 tx lanes
        #pragma unroll
        for (int i = 0; i < 4; i++) {
            float tm = fmaxf(s[i][0], s[i][1]);
            #pragma unroll
            for (int off = 8; off >= 1; off >>= 1)
                tm = fmaxf(tm, __shfl_xor_sync(0xffffffffu, tm, off, 16));
            float mnew  = fmaxf(mi[i], tm);
            float alpha = __expf(mi[i] - mnew);
            float p0 = __expf(s[i][0] - mnew);
            float p1 = __expf(s[i][1] - mnew);
            float rs = p0 + p1;
            #pragma unroll
            for (int off = 8; off >= 1; off >>= 1)
                rs += __shfl_xor_sync(0xffffffffu, rs, off, 16);
            li[i] = li[i] * alpha + rs;
            mi[i] = mnew;
            Ps[ty * 4 + i][tx * 2 + 0] = p0;
            Ps[ty * 4 + i][tx * 2 + 1] = p1;
            #pragma unroll
            for (int c = 0; c < 4; c++) acc[i][c] *= alpha;
        }
        __syncthreads();

        // O += P @ V  (4x4 per thread)
        #pragma unroll 4
        for (int j = 0; j < 32; j++) {
            float4 vv = *(const float4*)&Vs[j][tx * 4];
            #pragma unroll
            for (int i = 0; i < 4; i++) {
                float p = Ps[ty * 4 + i][j];
                acc[i][0] += p * vv.x;
                acc[i][1] += p * vv.y;
                acc[i][2] += p * vv.z;
                acc[i][3] += p * vv.w;
            }
        }
    }

    // normalize + write [B*T, C] layout (head h at column h*64)
    #pragma unroll
    for (int i = 0; i < 4; i++) {
        float inv = 1.f / li[i];
        float4 o = make_float4(acc[i][0] * inv, acc[i][1] * inv,
                               acc[i][2] * inv, acc[i][3] * inv);
        *(float4*)&outp[(size_t)(b * T_ + q0 + ty * 4 + i) * C_ + h * HD_ + tx * 4] = o;
    }
}

// ---------------------------------------------------------------------------
extern "C" void kernel_launch(void* const* d_in, const int* in_sizes, int n_in,
                              void* d_out, int out_size)
{
    const float* x     = (const float*)d_in[0];
    const float* Wqkv  = (const float*)d_in[1];
    const float* bqkv  = (const float*)d_in[2];
    const float* Wproj = (const float*)d_in[3];
    const float* bproj = (const float*)d_in[4];
    // d_in[5] = start_pos (always 0 here)
    float* out = (float*)d_out;

    float* qkv  = nullptr;
    float* attn = nullptr;
    cudaGetSymbolAddress((void**)&qkv,  g_qkv);
    cudaGetSymbolAddress((void**)&attn, g_attn);

    // 1) qkv = x @ Wqkv + bqkv   [4096, 2304]
    gemm_bias_kernel<<<dim3(C3_ / 128, MR_ / 128), 256>>>(x, Wqkv, bqkv, qkv,
                                                          MR_, C3_, C_);
    // 2) fused causal attention -> attn [4096, 768]
    attn_kernel<<<dim3(T_ / 64, NH_, B_), 256>>>(qkv, attn);
    // 3) out = attn @ Wproj + bproj   [4096, 768]
    gemm_bias_kernel<<<dim3(C_ / 128, MR_ / 128), 256>>>(attn, Wproj, bproj, out,
                                                         MR_, C_, C_);
}

// round 4
// speedup vs baseline: 1.1805x; 1.1805x over previous
#include <cuda_runtime.h>
#include <cstdint>
#include <math.h>

// Problem constants
constexpr int B_  = 4;
constexpr int T_  = 1024;
constexpr int C_  = 768;
constexpr int NH_ = 12;
constexpr int HD_ = 64;
constexpr int C3_ = 3 * C_;          // 2304
constexpr int MR_ = B_ * T_;         // 4096 rows

// Scratch (static device globals — no allocation)
__device__ float g_qkv[(size_t)MR_ * C3_];    // [4096, 2304]
__device__ float g_attn[(size_t)MR_ * C_];    // [4096, 768]

// ---------------------------------------------------------------------------
// helpers
// ---------------------------------------------------------------------------
__device__ __forceinline__ uint32_t smem_u32(const void* p) {
    uint32_t a;
    asm("{ .reg .u64 t; cvta.to.shared.u64 t, %1; cvt.u32.u64 %0, t; }"
        : "=r"(a) : "l"(p));
    return a;
}

__device__ __forceinline__ void cp_async16(uint32_t saddr, const void* gptr) {
    asm volatile("cp.async.cg.shared.global [%0], [%1], 16;"
                 :: "r"(saddr), "l"(gptr));
}
__device__ __forceinline__ void cp_commit() {
    asm volatile("cp.async.commit_group;");
}
template <int N>
__device__ __forceinline__ void cp_wait() {
    asm volatile("cp.async.wait_group %0;" :: "n"(N));
}

__device__ __forceinline__ uint32_t f2tf32(float x) {
    uint32_t r;
    asm("cvt.rna.tf32.f32 %0, %1;" : "=r"(r) : "f"(x));
    return r;
}

// split a float into hi (tf32) + lo (tf32 of residual)
__device__ __forceinline__ void tf32_split(float x, uint32_t& hi, uint32_t& lo) {
    hi = f2tf32(x);
    lo = f2tf32(x - __uint_as_float(hi));
}

__device__ __forceinline__ void mma_tf32(float* d, const uint32_t* a, const uint32_t* b) {
    asm volatile(
        "mma.sync.aligned.m16n8k8.row.col.f32.tf32.tf32.f32 "
        "{%0,%1,%2,%3}, {%4,%5,%6,%7}, {%8,%9}, {%0,%1,%2,%3};"
        : "+f"(d[0]), "+f"(d[1]), "+f"(d[2]), "+f"(d[3])
        : "r"(a[0]), "r"(a[1]), "r"(a[2]), "r"(a[3]), "r"(b[0]), "r"(b[1]));
}

// ---------------------------------------------------------------------------
// Tensor-core GEMM (3xTF32): C = A[M,K] @ B[K,N] + bias[N]
// CTA 128x128, BK=16, 256 threads (8 warps, 4x2 -> warp tile 32x64),
// 2-stage cp.async pipeline. Padded smem (A stride 20, B stride 136) ->
// conflict-free fragment loads.
// ---------------------------------------------------------------------------
__global__ __launch_bounds__(256) void gemm_mma_kernel(
    const float* __restrict__ A, const float* __restrict__ Bm,
    const float* __restrict__ bias, float* __restrict__ C,
    int M, int N, int K)
{
    constexpr int BM = 128, BN = 128, BK = 16;
    constexpr int AS = 20, BS = 136;           // padded strides (floats)
    __shared__ float As[2][BM][AS];
    __shared__ float Bs[2][BK][BS];

    const int tid  = threadIdx.x;
    const int wid  = tid >> 5;
    const int lane = tid & 31;
    const int m0 = blockIdx.y * BM;
    const int n0 = blockIdx.x * BN;
    const int wr = wid & 3;            // warp row (4)
    const int wc = wid >> 2;           // warp col (2)
    const int ry = wr * 32;
    const int cx = wc * 64;
    const int g = lane >> 2;           // 0..7
    const int c = lane & 3;            // 0..3

    float acc[2][8][4];
    #pragma unroll
    for (int mi = 0; mi < 2; mi++)
        #pragma unroll
        for (int ni = 0; ni < 8; ni++)
            #pragma unroll
            for (int j = 0; j < 4; j++) acc[mi][ni][j] = 0.f;

    const uint32_t asb = smem_u32(As);
    const uint32_t bsb = smem_u32(Bs);

    // per-thread load coords (A: 512 float4 chunks, B: 512 float4 chunks)
    const int arow0 = tid >> 2;            // id = tid     -> row 0..63
    const int ac4   = tid & 3;
    const int brow0 = tid >> 5;            // 0..7
    const int bc4   = tid & 31;

    auto load_tile = [&](int kt, int st) {
        const int k0 = kt * BK;
        #pragma unroll
        for (int i = 0; i < 2; i++) {
            int r = arow0 + i * 64;
            uint32_t sa = asb + (uint32_t)(((st * BM + r) * AS + ac4 * 4) * 4);
            cp_async16(sa, &A[(size_t)(m0 + r) * K + k0 + ac4 * 4]);
        }
        #pragma unroll
        for (int i = 0; i < 2; i++) {
            int r = brow0 + i * 8;
            uint32_t sb = bsb + (uint32_t)(((st * BK + r) * BS + bc4 * 4) * 4);
            cp_async16(sb, &Bm[(size_t)(k0 + r) * N + n0 + bc4 * 4]);
        }
    };

    const int KT = K / BK;
    load_tile(0, 0);
    cp_commit();

    for (int kt = 0; kt < KT; kt++) {
        const int st = kt & 1;
        if (kt + 1 < KT) load_tile(kt + 1, st ^ 1);
        cp_commit();
        cp_wait<1>();
        __syncthreads();

        #pragma unroll
        for (int step = 0; step < 2; step++) {
            const int k8 = step * 8;
            // A fragments (2 m-tiles) + 3xTF32 split
            uint32_t ah[2][4], al[2][4];
            #pragma unroll
            for (int mi = 0; mi < 2; mi++) {
                const int rb = ry + mi * 16;
                float a0 = As[st][rb + g][k8 + c];
                float a1 = As[st][rb + g + 8][k8 + c];
                float a2 = As[st][rb + g][k8 + c + 4];
                float a3 = As[st][rb + g + 8][k8 + c + 4];
                tf32_split(a0, ah[mi][0], al[mi][0]);
                tf32_split(a1, ah[mi][1], al[mi][1]);
                tf32_split(a2, ah[mi][2], al[mi][2]);
                tf32_split(a3, ah[mi][3], al[mi][3]);
            }
            // B fragments (8 n-tiles) + split  (b row = lane&3, col = lane>>2)
            uint32_t bh[8][2], bl[8][2];
            #pragma unroll
            for (int ni = 0; ni < 8; ni++) {
                float b0 = Bs[st][k8 + c][cx + ni * 8 + g];
                float b1 = Bs[st][k8 + c + 4][cx + ni * 8 + g];
                tf32_split(b0, bh[ni][0], bl[ni][0]);
                tf32_split(b1, bh[ni][1], bl[ni][1]);
            }
            #pragma unroll
            for (int mi = 0; mi < 2; mi++)
                #pragma unroll
                for (int ni = 0; ni < 8; ni++) {
                    mma_tf32(acc[mi][ni], ah[mi], bh[ni]);
                    mma_tf32(acc[mi][ni], ah[mi], bl[ni]);
                    mma_tf32(acc[mi][ni], al[mi], bh[ni]);
                }
        }
        __syncthreads();
    }

    // Epilogue: c frag (row=g, col=c*2) / (row+8)
    #pragma unroll
    for (int mi = 0; mi < 2; mi++) {
        #pragma unroll
        for (int ni = 0; ni < 8; ni++) {
            const int rr  = m0 + ry + mi * 16 + g;
            const int ccn = n0 + cx + ni * 8 + c * 2;
            float bx = bias[ccn], by = bias[ccn + 1];
            float2 o0 = make_float2(acc[mi][ni][0] + bx, acc[mi][ni][1] + by);
            float2 o1 = make_float2(acc[mi][ni][2] + bx, acc[mi][ni][3] + by);
            *(float2*)&C[(size_t)rr * N + ccn]       = o0;
            *(float2*)&C[(size_t)(rr + 8) * N + ccn] = o1;
        }
    }
}

// ---------------------------------------------------------------------------
// Fused causal flash attention (fp32, online softmax) — unchanged.
// Grid: (T/64, NH, B). Block: 256 threads (16x16).
// ---------------------------------------------------------------------------
__global__ __launch_bounds__(256) void attn_kernel(
    const float* __restrict__ qkv, float* __restrict__ outp)
{
    __shared__ float Qs[64][65];
    __shared__ float Ks[32][65];
    __shared__ float Vs[32][64];
    __shared__ float Ps[64][33];

    const int tid = threadIdx.x;
    const int ty = tid >> 4;
    const int tx = tid & 15;
    const int qt = blockIdx.x;
    const int h  = blockIdx.y;
    const int b  = blockIdx.z;
    const int q0 = qt * 64;
    const float scale = 0.125f;

    for (int i = tid; i < 64 * 16; i += 256) {
        int r  = i >> 4;
        int c4 = i & 15;
        float4 v = *(const float4*)&qkv[(size_t)(b * T_ + q0 + r) * C3_ + h * HD_ + c4 * 4];
        Qs[r][c4 * 4 + 0] = v.x;
        Qs[r][c4 * 4 + 1] = v.y;
        Qs[r][c4 * 4 + 2] = v.z;
        Qs[r][c4 * 4 + 3] = v.w;
    }

    float acc[4][4];
    float mi[4], li[4];
    #pragma unroll
    for (int i = 0; i < 4; i++) {
        mi[i] = -1e9f; li[i] = 0.f;
        #pragma unroll
        for (int c = 0; c < 4; c++) acc[i][c] = 0.f;
    }

    const int nkt = (q0 + 64) >> 5;
    for (int kt = 0; kt < nkt; kt++) {
        const int k0 = kt << 5;
        __syncthreads();
        for (int i = tid; i < 32 * 16; i += 256) {
            int r  = i >> 4;
            int c4 = i & 15;
            size_t base = (size_t)(b * T_ + k0 + r) * C3_ + h * HD_ + c4 * 4;
            float4 kv = *(const float4*)&qkv[base + C_];
            Ks[r][c4 * 4 + 0] = kv.x;
            Ks[r][c4 * 4 + 1] = kv.y;
            Ks[r][c4 * 4 + 2] = kv.z;
            Ks[r][c4 * 4 + 3] = kv.w;
            *(float4*)&Vs[r][c4 * 4] = *(const float4*)&qkv[base + 2 * C_];
        }
        __syncthreads();

        float s[4][2] = {{0.f,0.f},{0.f,0.f},{0.f,0.f},{0.f,0.f}};
        #pragma unroll 8
        for (int d = 0; d < 64; d++) {
            float q0f = Qs[ty * 4 + 0][d];
            float q1f = Qs[ty * 4 + 1][d];
            float q2f = Qs[ty * 4 + 2][d];
            float q3f = Qs[ty * 4 + 3][d];
            float k0f = Ks[tx * 2 + 0][d];
            float k1f = Ks[tx * 2 + 1][d];
            s[0][0] += q0f * k0f;  s[0][1] += q0f * k1f;
            s[1][0] += q1f * k0f;  s[1][1] += q1f * k1f;
            s[2][0] += q2f * k0f;  s[2][1] += q2f * k1f;
            s[3][0] += q3f * k0f;  s[3][1] += q3f * k1f;
        }
        #pragma unroll
        for (int i = 0; i < 4; i++) {
            int qg = q0 + ty * 4 + i;
            #pragma unroll
            for (int j = 0; j < 2; j++) {
                int kg = k0 + tx * 2 + j;
                s[i][j] = (kg <= qg) ? s[i][j] * scale : -1e9f;
            }
        }
        #pragma unroll
        for (int i = 0; i < 4; i++) {
            float tm = fmaxf(s[i][0], s[i][1]);
            #pragma unroll
            for (int off = 8; off >= 1; off >>= 1)
                tm = fmaxf(tm, __shfl_xor_sync(0xffffffffu, tm, off, 16));
            float mnew  = fmaxf(mi[i], tm);
            float alpha = __expf(mi[i] - mnew);
            float p0 = __expf(s[i][0] - mnew);
            float p1 = __expf(s[i][1] - mnew);
            float rs = p0 + p1;
            #pragma unroll
            for (int off = 8; off >= 1; off >>= 1)
                rs += __shfl_xor_sync(0xffffffffu, rs, off, 16);
            li[i] = li[i] * alpha + rs;
            mi[i] = mnew;
            Ps[ty * 4 + i][tx * 2 + 0] = p0;
            Ps[ty * 4 + i][tx * 2 + 1] = p1;
            #pragma unroll
            for (int c = 0; c < 4; c++) acc[i][c] *= alpha;
        }
        __syncthreads();

        #pragma unroll 4
        for (int j = 0; j < 32; j++) {
            float4 vv = *(const float4*)&Vs[j][tx * 4];
            #pragma unroll
            for (int i = 0; i < 4; i++) {
                float p = Ps[ty * 4 + i][j];
                acc[i][0] += p * vv.x;
                acc[i][1] += p * vv.y;
                acc[i][2] += p * vv.z;
                acc[i][3] += p * vv.w;
            }
        }
    }

    #pragma unroll
    for (int i = 0; i < 4; i++) {
        float inv = 1.f / li[i];
        float4 o = make_float4(acc[i][0] * inv, acc[i][1] * inv,
                               acc[i][2] * inv, acc[i][3] * inv);
        *(float4*)&outp[(size_t)(b * T_ + q0 + ty * 4 + i) * C_ + h * HD_ + tx * 4] = o;
    }
}

// ---------------------------------------------------------------------------
extern "C" void kernel_launch(void* const* d_in, const int* in_sizes, int n_in,
                              void* d_out, int out_size)
{
    const float* x     = (const float*)d_in[0];
    const float* Wqkv  = (const float*)d_in[1];
    const float* bqkv  = (const float*)d_in[2];
    const float* Wproj = (const float*)d_in[3];
    const float* bproj = (const float*)d_in[4];
    float* out = (float*)d_out;

    float* qkv  = nullptr;
    float* attn = nullptr;
    cudaGetSymbolAddress((void**)&qkv,  g_qkv);
    cudaGetSymbolAddress((void**)&attn, g_attn);

    // 1) qkv = x @ Wqkv + bqkv   [4096, 2304]   (mma.sync 3xTF32)
    gemm_mma_kernel<<<dim3(C3_ / 128, MR_ / 128), 256>>>(x, Wqkv, bqkv, qkv,
                                                         MR_, C3_, C_);
    // 2) fused causal attention -> attn [4096, 768]
    attn_kernel<<<dim3(T_ / 64, NH_, B_), 256>>>(qkv, attn);
    // 3) out = attn @ Wproj + bproj   [4096, 768]   (mma.sync 3xTF32)
    gemm_mma_kernel<<<dim3(C_ / 128, MR_ / 128), 256>>>(attn, Wproj, bproj, out,
                                                        MR_, C_, C_);
}

// round 5
// speedup vs baseline: 1.5442x; 1.3082x over previous
#include <cuda_runtime.h>
#include <cuda_bf16.h>
#include <cstdint>
#include <math.h>

// Problem constants
constexpr int B_  = 4;
constexpr int T_  = 1024;
constexpr int C_  = 768;
constexpr int NH_ = 12;
constexpr int HD_ = 64;
constexpr int C3_ = 3 * C_;          // 2304
constexpr int MR_ = B_ * T_;         // 4096 rows

// Scratch (static device globals — no allocation)
__device__ float g_qkv[(size_t)MR_ * C3_];                 // [4096, 2304] fp32
__device__ __nv_bfloat16 g_xh[(size_t)MR_ * C_];
__device__ __nv_bfloat16 g_xl[(size_t)MR_ * C_];
__device__ __nv_bfloat16 g_wqh[(size_t)C_ * C3_];
__device__ __nv_bfloat16 g_wql[(size_t)C_ * C3_];
__device__ __nv_bfloat16 g_wph[(size_t)C_ * C_];
__device__ __nv_bfloat16 g_wpl[(size_t)C_ * C_];
__device__ __nv_bfloat16 g_ah[(size_t)MR_ * C_];           // attention out hi
__device__ __nv_bfloat16 g_al[(size_t)MR_ * C_];           // attention out lo

// ---------------------------------------------------------------------------
// helpers
// ---------------------------------------------------------------------------
__device__ __forceinline__ uint32_t smem_u32(const void* p) {
    uint32_t a;
    asm("{ .reg .u64 t; cvta.to.shared.u64 t, %1; cvt.u32.u64 %0, t; }"
        : "=r"(a) : "l"(p));
    return a;
}
__device__ __forceinline__ void cp_async16(uint32_t saddr, const void* gptr) {
    asm volatile("cp.async.cg.shared.global [%0], [%1], 16;"
                 :: "r"(saddr), "l"(gptr));
}
__device__ __forceinline__ void cp_commit() {
    asm volatile("cp.async.commit_group;");
}
template <int N>
__device__ __forceinline__ void cp_wait() {
    asm volatile("cp.async.wait_group %0;" :: "n"(N));
}

__device__ __forceinline__ void ldm_x4(uint32_t* r, uint32_t addr) {
    asm volatile("ldmatrix.sync.aligned.m8n8.x4.shared.b16 {%0,%1,%2,%3}, [%4];"
                 : "=r"(r[0]), "=r"(r[1]), "=r"(r[2]), "=r"(r[3]) : "r"(addr));
}
__device__ __forceinline__ void ldm_x4_t(uint32_t* r, uint32_t addr) {
    asm volatile("ldmatrix.sync.aligned.m8n8.x4.trans.shared.b16 {%0,%1,%2,%3}, [%4];"
                 : "=r"(r[0]), "=r"(r[1]), "=r"(r[2]), "=r"(r[3]) : "r"(addr));
}
__device__ __forceinline__ void mma_bf16(float* d, const uint32_t* a, const uint32_t* b) {
    asm volatile(
        "mma.sync.aligned.m16n8k16.row.col.f32.bf16.bf16.f32 "
        "{%0,%1,%2,%3}, {%4,%5,%6,%7}, {%8,%9}, {%0,%1,%2,%3};"
        : "+f"(d[0]), "+f"(d[1]), "+f"(d[2]), "+f"(d[3])
        : "r"(a[0]), "r"(a[1]), "r"(a[2]), "r"(a[3]), "r"(b[0]), "r"(b[1]));
}

__device__ __forceinline__ uint32_t pack_bf16(float x, float y) {
    __nv_bfloat16 bx = __float2bfloat16(x), by = __float2bfloat16(y);
    return (uint32_t)__bfloat16_as_ushort(bx) |
           ((uint32_t)__bfloat16_as_ushort(by) << 16);
}

// ---------------------------------------------------------------------------
// split: fp32 -> bf16 hi + bf16 lo(residual)
// ---------------------------------------------------------------------------
__global__ __launch_bounds__(256) void split_kernel(
    const float* __restrict__ src, __nv_bfloat16* __restrict__ hi,
    __nv_bfloat16* __restrict__ lo, int n)
{
    int i = (blockIdx.x * 256 + threadIdx.x) * 4;
    if (i >= n) return;
    float4 v = *(const float4*)&src[i];
    float f[4] = {v.x, v.y, v.z, v.w};
    uint32_t h[2], l[2];
    float hf[4];
    #pragma unroll
    for (int j = 0; j < 4; j++)
        hf[j] = __bfloat162float(__float2bfloat16(f[j]));
    h[0] = pack_bf16(f[0], f[1]);
    h[1] = pack_bf16(f[2], f[3]);
    l[0] = pack_bf16(f[0] - hf[0], f[1] - hf[1]);
    l[1] = pack_bf16(f[2] - hf[2], f[3] - hf[3]);
    *(uint2*)&hi[i] = make_uint2(h[0], h[1]);
    *(uint2*)&lo[i] = make_uint2(l[0], l[1]);
}

// ---------------------------------------------------------------------------
// Tensor-core GEMM (bf16 hi/lo emulation): C = A[M,K] @ B[K,N] + bias[N]
// CTA 128x128, BK=16, 256 threads (8 warps 4x2, warp tile 32x64),
// 2-stage cp.async pipeline, ldmatrix fragments.
// Per logical MAC: 3 bf16 MMAs (ah*bh + ah*bl + al*bh).
// ---------------------------------------------------------------------------
__global__ __launch_bounds__(256) void gemm_bf16x3_kernel(
    const __nv_bfloat16* __restrict__ Ah, const __nv_bfloat16* __restrict__ Al,
    const __nv_bfloat16* __restrict__ Bh, const __nv_bfloat16* __restrict__ Bl,
    const float* __restrict__ bias, float* __restrict__ C,
    int M, int N, int K)
{
    constexpr int BM = 128, BN = 128, BK = 16;
    constexpr int ASB = 24;    // A smem stride (bf16): 48 B/row
    constexpr int BSB = 136;   // B smem stride (bf16): 272 B/row
    __shared__ __nv_bfloat16 sAh[2][BM][ASB];
    __shared__ __nv_bfloat16 sAl[2][BM][ASB];
    __shared__ __nv_bfloat16 sBh[2][BK][BSB];
    __shared__ __nv_bfloat16 sBl[2][BK][BSB];

    const int tid  = threadIdx.x;
    const int wid  = tid >> 5;
    const int lane = tid & 31;
    const int m0 = blockIdx.y * BM;
    const int n0 = blockIdx.x * BN;
    const int ry = (wid & 3) * 32;
    const int cx = (wid >> 2) * 64;
    const int g = lane >> 2;           // 0..7
    const int c = lane & 3;            // 0..3

    float acc[2][8][4];
    #pragma unroll
    for (int mi = 0; mi < 2; mi++)
        #pragma unroll
        for (int ni = 0; ni < 8; ni++)
            #pragma unroll
            for (int j = 0; j < 4; j++) acc[mi][ni][j] = 0.f;

    const uint32_t sAhB = smem_u32(sAh);
    const uint32_t sAlB = smem_u32(sAl);
    const uint32_t sBhB = smem_u32(sBh);
    const uint32_t sBlB = smem_u32(sBl);

    // load mapping
    const int arow = tid >> 1;          // 0..127
    const int ahalf = tid & 1;          // 8-elt half
    const int brow = tid >> 4;          // 0..15
    const int bc   = tid & 15;          // 8-elt chunk

    auto load_tile = [&](int kt, int st) {
        const int k0 = kt * BK;
        const size_t ga = (size_t)(m0 + arow) * K + k0 + ahalf * 8;
        const size_t gb = (size_t)(k0 + brow) * N + n0 + bc * 8;
        const uint32_t oa = (uint32_t)(((st * BM + arow) * ASB + ahalf * 8) * 2);
        const uint32_t ob = (uint32_t)(((st * BK + brow) * BSB + bc * 8) * 2);
        cp_async16(sAhB + oa, &Ah[ga]);
        cp_async16(sAlB + oa, &Al[ga]);
        cp_async16(sBhB + ob, &Bh[gb]);
        cp_async16(sBlB + ob, &Bl[gb]);
    };

    const int KT = K / BK;
    load_tile(0, 0);
    cp_commit();

    // ldmatrix lane addresses (element offsets within a stage)
    const int a_r = lane & 15;                 // m within 16-row tile
    const int a_k = (lane >> 4) * 8;           // k-block
    const int b_k = (lane & 7) + ((lane >> 3) & 1) * 8;
    const int b_n = (lane >> 4) * 8;

    for (int kt = 0; kt < KT; kt++) {
        const int st = kt & 1;
        if (kt + 1 < KT) load_tile(kt + 1, st ^ 1);
        cp_commit();
        cp_wait<1>();
        __syncthreads();

        uint32_t ah[2][4], al[2][4], bh[8][2], bl[8][2];
        #pragma unroll
        for (int mi = 0; mi < 2; mi++) {
            uint32_t off = (uint32_t)(((st * BM + ry + mi * 16 + a_r) * ASB + a_k) * 2);
            ldm_x4(ah[mi], sAhB + off);
            ldm_x4(al[mi], sAlB + off);
        }
        #pragma unroll
        for (int nb = 0; nb < 4; nb++) {
            uint32_t off = (uint32_t)(((st * BK + b_k) * BSB + cx + nb * 16 + b_n) * 2);
            uint32_t rh[4], rl[4];
            ldm_x4_t(rh, sBhB + off);
            ldm_x4_t(rl, sBlB + off);
            bh[nb * 2 + 0][0] = rh[0]; bh[nb * 2 + 0][1] = rh[1];
            bh[nb * 2 + 1][0] = rh[2]; bh[nb * 2 + 1][1] = rh[3];
            bl[nb * 2 + 0][0] = rl[0]; bl[nb * 2 + 0][1] = rl[1];
            bl[nb * 2 + 1][0] = rl[2]; bl[nb * 2 + 1][1] = rl[3];
        }
        #pragma unroll
        for (int mi = 0; mi < 2; mi++)
            #pragma unroll
            for (int ni = 0; ni < 8; ni++) {
                mma_bf16(acc[mi][ni], ah[mi], bh[ni]);
                mma_bf16(acc[mi][ni], ah[mi], bl[ni]);
                mma_bf16(acc[mi][ni], al[mi], bh[ni]);
            }
        __syncthreads();
    }

    // Epilogue (c frag: rows g / g+8, cols c*2, c*2+1)
    #pragma unroll
    for (int mi = 0; mi < 2; mi++) {
        #pragma unroll
        for (int ni = 0; ni < 8; ni++) {
            const int rr  = m0 + ry + mi * 16 + g;
            const int ccn = n0 + cx + ni * 8 + c * 2;
            float bx = bias[ccn], by = bias[ccn + 1];
            float2 o0 = make_float2(acc[mi][ni][0] + bx, acc[mi][ni][1] + by);
            float2 o1 = make_float2(acc[mi][ni][2] + bx, acc[mi][ni][3] + by);
            *(float2*)&C[(size_t)rr * N + ccn]       = o0;
            *(float2*)&C[(size_t)(rr + 8) * N + ccn] = o1;
        }
    }
}

// ---------------------------------------------------------------------------
// Fused causal flash attention (fp32, online softmax).
// Writes output directly as bf16 hi/lo for the proj GEMM.
// Grid: (T/64, NH, B). Block: 256 threads (16x16).
// ---------------------------------------------------------------------------
__global__ __launch_bounds__(256) void attn_kernel(
    const float* __restrict__ qkv,
    __nv_bfloat16* __restrict__ oh, __nv_bfloat16* __restrict__ ol)
{
    __shared__ float Qs[64][65];
    __shared__ float Ks[32][65];
    __shared__ float Vs[32][64];
    __shared__ float Ps[64][33];

    const int tid = threadIdx.x;
    const int ty = tid >> 4;
    const int tx = tid & 15;
    const int qt = blockIdx.x;
    const int h  = blockIdx.y;
    const int b  = blockIdx.z;
    const int q0 = qt * 64;
    const float scale = 0.125f;

    for (int i = tid; i < 64 * 16; i += 256) {
        int r  = i >> 4;
        int c4 = i & 15;
        float4 v = *(const float4*)&qkv[(size_t)(b * T_ + q0 + r) * C3_ + h * HD_ + c4 * 4];
        Qs[r][c4 * 4 + 0] = v.x;
        Qs[r][c4 * 4 + 1] = v.y;
        Qs[r][c4 * 4 + 2] = v.z;
        Qs[r][c4 * 4 + 3] = v.w;
    }

    float acc[4][4];
    float mi[4], li[4];
    #pragma unroll
    for (int i = 0; i < 4; i++) {
        mi[i] = -1e9f; li[i] = 0.f;
        #pragma unroll
        for (int c = 0; c < 4; c++) acc[i][c] = 0.f;
    }

    const int nkt = (q0 + 64) >> 5;
    for (int kt = 0; kt < nkt; kt++) {
        const int k0 = kt << 5;
        __syncthreads();
        for (int i = tid; i < 32 * 16; i += 256) {
            int r  = i >> 4;
            int c4 = i & 15;
            size_t base = (size_t)(b * T_ + k0 + r) * C3_ + h * HD_ + c4 * 4;
            float4 kv = *(const float4*)&qkv[base + C_];
            Ks[r][c4 * 4 + 0] = kv.x;
            Ks[r][c4 * 4 + 1] = kv.y;
            Ks[r][c4 * 4 + 2] = kv.z;
            Ks[r][c4 * 4 + 3] = kv.w;
            *(float4*)&Vs[r][c4 * 4] = *(const float4*)&qkv[base + 2 * C_];
        }
        __syncthreads();

        float s[4][2] = {{0.f,0.f},{0.f,0.f},{0.f,0.f},{0.f,0.f}};
        #pragma unroll 8
        for (int d = 0; d < 64; d++) {
            float q0f = Qs[ty * 4 + 0][d];
            float q1f = Qs[ty * 4 + 1][d];
            float q2f = Qs[ty * 4 + 2][d];
            float q3f = Qs[ty * 4 + 3][d];
            float k0f = Ks[tx * 2 + 0][d];
            float k1f = Ks[tx * 2 + 1][d];
            s[0][0] += q0f * k0f;  s[0][1] += q0f * k1f;
            s[1][0] += q1f * k0f;  s[1][1] += q1f * k1f;
            s[2][0] += q2f * k0f;  s[2][1] += q2f * k1f;
            s[3][0] += q3f * k0f;  s[3][1] += q3f * k1f;
        }
        #pragma unroll
        for (int i = 0; i < 4; i++) {
            int qg = q0 + ty * 4 + i;
            #pragma unroll
            for (int j = 0; j < 2; j++) {
                int kg = k0 + tx * 2 + j;
                s[i][j] = (kg <= qg) ? s[i][j] * scale : -1e9f;
            }
        }
        #pragma unroll
        for (int i = 0; i < 4; i++) {
            float tm = fmaxf(s[i][0], s[i][1]);
            #pragma unroll
            for (int off = 8; off >= 1; off >>= 1)
                tm = fmaxf(tm, __shfl_xor_sync(0xffffffffu, tm, off, 16));
            float mnew  = fmaxf(mi[i], tm);
            float alpha = __expf(mi[i] - mnew);
            float p0 = __expf(s[i][0] - mnew);
            float p1 = __expf(s[i][1] - mnew);
            float rs = p0 + p1;
            #pragma unroll
            for (int off = 8; off >= 1; off >>= 1)
                rs += __shfl_xor_sync(0xffffffffu, rs, off, 16);
            li[i] = li[i] * alpha + rs;
            mi[i] = mnew;
            Ps[ty * 4 + i][tx * 2 + 0] = p0;
            Ps[ty * 4 + i][tx * 2 + 1] = p1;
            #pragma unroll
            for (int c = 0; c < 4; c++) acc[i][c] *= alpha;
        }
        __syncthreads();

        #pragma unroll 4
        for (int j = 0; j < 32; j++) {
            float4 vv = *(const float4*)&Vs[j][tx * 4];
            #pragma unroll
            for (int i = 0; i < 4; i++) {
                float p = Ps[ty * 4 + i][j];
                acc[i][0] += p * vv.x;
                acc[i][1] += p * vv.y;
                acc[i][2] += p * vv.z;
                acc[i][3] += p * vv.w;
            }
        }
    }

    #pragma unroll
    for (int i = 0; i < 4; i++) {
        float inv = 1.f / li[i];
        float o[4];
        #pragma unroll
        for (int c = 0; c < 4; c++) o[c] = acc[i][c] * inv;
        float hf[4];
        #pragma unroll
        for (int c = 0; c < 4; c++)
            hf[c] = __bfloat162float(__float2bfloat16(o[c]));
        size_t idx = (size_t)(b * T_ + q0 + ty * 4 + i) * C_ + h * HD_ + tx * 4;
        *(uint2*)&oh[idx] = make_uint2(pack_bf16(o[0], o[1]), pack_bf16(o[2], o[3]));
        *(uint2*)&ol[idx] = make_uint2(pack_bf16(o[0] - hf[0], o[1] - hf[1]),
                                       pack_bf16(o[2] - hf[2], o[3] - hf[3]));
    }
}

// ---------------------------------------------------------------------------
extern "C" void kernel_launch(void* const* d_in, const int* in_sizes, int n_in,
                              void* d_out, int out_size)
{
    const float* x     = (const float*)d_in[0];
    const float* Wqkv  = (const float*)d_in[1];
    const float* bqkv  = (const float*)d_in[2];
    const float* Wproj = (const float*)d_in[3];
    const float* bproj = (const float*)d_in[4];
    float* out = (float*)d_out;

    float* qkv = nullptr;
    __nv_bfloat16 *xh, *xl, *wqh, *wql, *wph, *wpl, *ah, *al;
    cudaGetSymbolAddress((void**)&qkv, g_qkv);
    cudaGetSymbolAddress((void**)&xh,  g_xh);
    cudaGetSymbolAddress((void**)&xl,  g_xl);
    cudaGetSymbolAddress((void**)&wqh, g_wqh);
    cudaGetSymbolAddress((void**)&wql, g_wql);
    cudaGetSymbolAddress((void**)&wph, g_wph);
    cudaGetSymbolAddress((void**)&wpl, g_wpl);
    cudaGetSymbolAddress((void**)&ah,  g_ah);
    cudaGetSymbolAddress((void**)&al,  g_al);

    // 0) split inputs into bf16 hi/lo
    split_kernel<<<(MR_ * C_) / 1024, 256>>>(x, xh, xl, MR_ * C_);
    split_kernel<<<(C_ * C3_) / 1024, 256>>>(Wqkv, wqh, wql, C_ * C3_);
    split_kernel<<<(C_ * C_) / 1024, 256>>>(Wproj, wph, wpl, C_ * C_);

    // 1) qkv = x @ Wqkv + bqkv   [4096, 2304]   (bf16x3 mma)
    gemm_bf16x3_kernel<<<dim3(C3_ / 128, MR_ / 128), 256>>>(
        xh, xl, wqh, wql, bqkv, qkv, MR_, C3_, C_);
    // 2) fused causal attention -> bf16 hi/lo [4096, 768]
    attn_kernel<<<dim3(T_ / 64, NH_, B_), 256>>>(qkv, ah, al);
    // 3) out = attn @ Wproj + bproj   [4096, 768]   (bf16x3 mma)
    gemm_bf16x3_kernel<<<dim3(C_ / 128, MR_ / 128), 256>>>(
        ah, al, wph, wpl, bproj, out, MR_, C_, C_);
}

// round 6
// speedup vs baseline: 2.7233x; 1.7635x over previous
#include <cuda_runtime.h>
#include <cuda_bf16.h>
#include <cuda_fp16.h>
#include <cstdint>
#include <math.h>

// Problem constants
constexpr int B_  = 4;
constexpr int T_  = 1024;
constexpr int C_  = 768;
constexpr int NH_ = 12;
constexpr int HD_ = 64;
constexpr int C3_ = 3 * C_;          // 2304
constexpr int MR_ = B_ * T_;         // 4096 rows

// Scratch (static device globals — no allocation)
__device__ float g_qkv[(size_t)MR_ * C3_];                 // [4096, 2304] fp32
__device__ __nv_bfloat16 g_xh[(size_t)MR_ * C_];
__device__ __nv_bfloat16 g_xl[(size_t)MR_ * C_];
__device__ __nv_bfloat16 g_wqh[(size_t)C_ * C3_];
__device__ __nv_bfloat16 g_wql[(size_t)C_ * C3_];
__device__ __nv_bfloat16 g_wph[(size_t)C_ * C_];
__device__ __nv_bfloat16 g_wpl[(size_t)C_ * C_];
__device__ __nv_bfloat16 g_ah[(size_t)MR_ * C_];           // attention out hi
__device__ __nv_bfloat16 g_al[(size_t)MR_ * C_];           // attention out lo
// f16 hi/lo splits of q,k,v  (each [4096][768], head-interleaved layout)
__device__ __half g_fqh[(size_t)MR_ * C_];
__device__ __half g_fql[(size_t)MR_ * C_];
__device__ __half g_fkh[(size_t)MR_ * C_];
__device__ __half g_fkl[(size_t)MR_ * C_];
__device__ __half g_fvh[(size_t)MR_ * C_];
__device__ __half g_fvl[(size_t)MR_ * C_];

// ---------------------------------------------------------------------------
// helpers
// ---------------------------------------------------------------------------
__device__ __forceinline__ uint32_t smem_u32(const void* p) {
    uint32_t a;
    asm("{ .reg .u64 t; cvta.to.shared.u64 t, %1; cvt.u32.u64 %0, t; }"
        : "=r"(a) : "l"(p));
    return a;
}
__device__ __forceinline__ void cp_async16(uint32_t saddr, const void* gptr) {
    asm volatile("cp.async.cg.shared.global [%0], [%1], 16;"
                 :: "r"(saddr), "l"(gptr));
}
__device__ __forceinline__ void cp_commit() {
    asm volatile("cp.async.commit_group;");
}
template <int N>
__device__ __forceinline__ void cp_wait() {
    asm volatile("cp.async.wait_group %0;" :: "n"(N));
}
__device__ __forceinline__ void ldm_x4(uint32_t* r, uint32_t addr) {
    asm volatile("ldmatrix.sync.aligned.m8n8.x4.shared.b16 {%0,%1,%2,%3}, [%4];"
                 : "=r"(r[0]), "=r"(r[1]), "=r"(r[2]), "=r"(r[3]) : "r"(addr));
}
__device__ __forceinline__ void ldm_x4_t(uint32_t* r, uint32_t addr) {
    asm volatile("ldmatrix.sync.aligned.m8n8.x4.trans.shared.b16 {%0,%1,%2,%3}, [%4];"
                 : "=r"(r[0]), "=r"(r[1]), "=r"(r[2]), "=r"(r[3]) : "r"(addr));
}
__device__ __forceinline__ void ldm_x2_t(uint32_t* r, uint32_t addr) {
    asm volatile("ldmatrix.sync.aligned.m8n8.x2.trans.shared.b16 {%0,%1}, [%2];"
                 : "=r"(r[0]), "=r"(r[1]) : "r"(addr));
}
__device__ __forceinline__ void mma_bf16(float* d, const uint32_t* a, const uint32_t* b) {
    asm volatile(
        "mma.sync.aligned.m16n8k16.row.col.f32.bf16.bf16.f32 "
        "{%0,%1,%2,%3}, {%4,%5,%6,%7}, {%8,%9}, {%0,%1,%2,%3};"
        : "+f"(d[0]), "+f"(d[1]), "+f"(d[2]), "+f"(d[3])
        : "r"(a[0]), "r"(a[1]), "r"(a[2]), "r"(a[3]), "r"(b[0]), "r"(b[1]));
}
__device__ __forceinline__ void mma_f16(float* d, const uint32_t* a, const uint32_t* b) {
    asm volatile(
        "mma.sync.aligned.m16n8k16.row.col.f32.f16.f16.f32 "
        "{%0,%1,%2,%3}, {%4,%5,%6,%7}, {%8,%9}, {%0,%1,%2,%3};"
        : "+f"(d[0]), "+f"(d[1]), "+f"(d[2]), "+f"(d[3])
        : "r"(a[0]), "r"(a[1]), "r"(a[2]), "r"(a[3]), "r"(b[0]), "r"(b[1]));
}
__device__ __forceinline__ uint32_t pack_bf16(float x, float y) {
    __nv_bfloat16 bx = __float2bfloat16(x), by = __float2bfloat16(y);
    return (uint32_t)__bfloat16_as_ushort(bx) |
           ((uint32_t)__bfloat16_as_ushort(by) << 16);
}
__device__ __forceinline__ uint32_t cvt_f16x2(float hi, float lo) {
    uint32_t r;
    asm("cvt.rn.f16x2.f32 %0, %1, %2;" : "=r"(r) : "f"(hi), "f"(lo));
    return r;
}
__device__ __forceinline__ uint32_t ex2_f16x2(uint32_t x) {
    uint32_t r;
    asm("ex2.approx.f16x2 %0, %1;" : "=r"(r) : "r"(x));
    return r;
}
__device__ __forceinline__ float fex2(float x) {
    float r;
    asm("ex2.approx.f32 %0, %1;" : "=f"(r) : "f"(x));
    return r;
}

// ---------------------------------------------------------------------------
// split: fp32 -> bf16 hi + bf16 lo (for GEMM inputs)
// ---------------------------------------------------------------------------
__global__ __launch_bounds__(256) void split_kernel(
    const float* __restrict__ src, __nv_bfloat16* __restrict__ hi,
    __nv_bfloat16* __restrict__ lo, int n)
{
    int i = (blockIdx.x * 256 + threadIdx.x) * 4;
    if (i >= n) return;
    float4 v = *(const float4*)&src[i];
    float f[4] = {v.x, v.y, v.z, v.w};
    float hf[4];
    #pragma unroll
    for (int j = 0; j < 4; j++)
        hf[j] = __bfloat162float(__float2bfloat16(f[j]));
    uint32_t h0 = pack_bf16(f[0], f[1]), h1 = pack_bf16(f[2], f[3]);
    uint32_t l0 = pack_bf16(f[0] - hf[0], f[1] - hf[1]);
    uint32_t l1 = pack_bf16(f[2] - hf[2], f[3] - hf[3]);
    *(uint2*)&hi[i] = make_uint2(h0, h1);
    *(uint2*)&lo[i] = make_uint2(l0, l1);
}

// ---------------------------------------------------------------------------
// split qkv (fp32 [4096][2304]) -> q/k/v f16 hi/lo ([4096][768] each)
// ---------------------------------------------------------------------------
__global__ __launch_bounds__(256) void split_qkv_kernel(
    const float* __restrict__ qkv,
    __half* __restrict__ qh, __half* __restrict__ ql,
    __half* __restrict__ kh, __half* __restrict__ kl,
    __half* __restrict__ vh, __half* __restrict__ vl)
{
    int i4 = (blockIdx.x * 256 + threadIdx.x) * 4;
    if (i4 >= MR_ * C3_) return;
    int row = i4 / C3_;
    int col = i4 - row * C3_;
    int sec = col / C_;
    int w   = col - sec * C_;
    __half* hd = (sec == 0) ? qh : (sec == 1) ? kh : vh;
    __half* ld = (sec == 0) ? ql : (sec == 1) ? kl : vl;
    float4 v = *(const float4*)&qkv[i4];
    float f[4] = {v.x, v.y, v.z, v.w};
    uint16_t hh[4], ll[4];
    #pragma unroll
    for (int j = 0; j < 4; j++) {
        __half hj = __float2half_rn(f[j]);
        hh[j] = __half_as_ushort(hj);
        ll[j] = __half_as_ushort(__float2half_rn(f[j] - __half2float(hj)));
    }
    size_t dst = (size_t)row * C_ + w;
    *(uint2*)&hd[dst] = make_uint2((uint32_t)hh[0] | ((uint32_t)hh[1] << 16),
                                   (uint32_t)hh[2] | ((uint32_t)hh[3] << 16));
    *(uint2*)&ld[dst] = make_uint2((uint32_t)ll[0] | ((uint32_t)ll[1] << 16),
                                   (uint32_t)ll[2] | ((uint32_t)ll[3] << 16));
}

// ---------------------------------------------------------------------------
// Tensor-core GEMM (bf16 hi/lo x3): C = A[M,K] @ B[K,N] + bias[N]  (as R5)
// ---------------------------------------------------------------------------
__global__ __launch_bounds__(256) void gemm_bf16x3_kernel(
    const __nv_bfloat16* __restrict__ Ah, const __nv_bfloat16* __restrict__ Al,
    const __nv_bfloat16* __restrict__ Bh, const __nv_bfloat16* __restrict__ Bl,
    const float* __restrict__ bias, float* __restrict__ C,
    int M, int N, int K)
{
    constexpr int BM = 128, BN = 128, BK = 16;
    constexpr int ASB = 24;
    constexpr int BSB = 136;
    __shared__ __nv_bfloat16 sAh[2][BM][ASB];
    __shared__ __nv_bfloat16 sAl[2][BM][ASB];
    __shared__ __nv_bfloat16 sBh[2][BK][BSB];
    __shared__ __nv_bfloat16 sBl[2][BK][BSB];

    const int tid  = threadIdx.x;
    const int wid  = tid >> 5;
    const int lane = tid & 31;
    const int m0 = blockIdx.y * BM;
    const int n0 = blockIdx.x * BN;
    const int ry = (wid & 3) * 32;
    const int cx = (wid >> 2) * 64;
    const int g = lane >> 2;
    const int c = lane & 3;

    float acc[2][8][4];
    #pragma unroll
    for (int mi = 0; mi < 2; mi++)
        #pragma unroll
        for (int ni = 0; ni < 8; ni++)
            #pragma unroll
            for (int j = 0; j < 4; j++) acc[mi][ni][j] = 0.f;

    const uint32_t sAhB = smem_u32(sAh);
    const uint32_t sAlB = smem_u32(sAl);
    const uint32_t sBhB = smem_u32(sBh);
    const uint32_t sBlB = smem_u32(sBl);

    const int arow = tid >> 1;
    const int ahalf = tid & 1;
    const int brow = tid >> 4;
    const int bc   = tid & 15;

    auto load_tile = [&](int kt, int st) {
        const int k0 = kt * BK;
        const size_t ga = (size_t)(m0 + arow) * K + k0 + ahalf * 8;
        const size_t gb = (size_t)(k0 + brow) * N + n0 + bc * 8;
        const uint32_t oa = (uint32_t)(((st * BM + arow) * ASB + ahalf * 8) * 2);
        const uint32_t ob = (uint32_t)(((st * BK + brow) * BSB + bc * 8) * 2);
        cp_async16(sAhB + oa, &Ah[ga]);
        cp_async16(sAlB + oa, &Al[ga]);
        cp_async16(sBhB + ob, &Bh[gb]);
        cp_async16(sBlB + ob, &Bl[gb]);
    };

    const int KT = K / BK;
    load_tile(0, 0);
    cp_commit();

    const int a_r = lane & 15;
    const int a_k = (lane >> 4) * 8;
    const int b_k = (lane & 7) + ((lane >> 3) & 1) * 8;
    const int b_n = (lane >> 4) * 8;

    for (int kt = 0; kt < KT; kt++) {
        const int st = kt & 1;
        if (kt + 1 < KT) load_tile(kt + 1, st ^ 1);
        cp_commit();
        cp_wait<1>();
        __syncthreads();

        uint32_t ah[2][4], al[2][4], bh[8][2], bl[8][2];
        #pragma unroll
        for (int mi = 0; mi < 2; mi++) {
            uint32_t off = (uint32_t)(((st * BM + ry + mi * 16 + a_r) * ASB + a_k) * 2);
            ldm_x4(ah[mi], sAhB + off);
            ldm_x4(al[mi], sAlB + off);
        }
        #pragma unroll
        for (int nb = 0; nb < 4; nb++) {
            uint32_t off = (uint32_t)(((st * BK + b_k) * BSB + cx + nb * 16 + b_n) * 2);
            uint32_t rh[4], rl[4];
            ldm_x4_t(rh, sBhB + off);
            ldm_x4_t(rl, sBlB + off);
            bh[nb * 2 + 0][0] = rh[0]; bh[nb * 2 + 0][1] = rh[1];
            bh[nb * 2 + 1][0] = rh[2]; bh[nb * 2 + 1][1] = rh[3];
            bl[nb * 2 + 0][0] = rl[0]; bl[nb * 2 + 0][1] = rl[1];
            bl[nb * 2 + 1][0] = rl[2]; bl[nb * 2 + 1][1] = rl[3];
        }
        #pragma unroll
        for (int mi = 0; mi < 2; mi++)
            #pragma unroll
            for (int ni = 0; ni < 8; ni++) {
                mma_bf16(acc[mi][ni], ah[mi], bh[ni]);
                mma_bf16(acc[mi][ni], ah[mi], bl[ni]);
                mma_bf16(acc[mi][ni], al[mi], bh[ni]);
            }
        __syncthreads();
    }

    #pragma unroll
    for (int mi = 0; mi < 2; mi++) {
        #pragma unroll
        for (int ni = 0; ni < 8; ni++) {
            const int rr  = m0 + ry + mi * 16 + g;
            const int ccn = n0 + cx + ni * 8 + c * 2;
            float bx = bias[ccn], by = bias[ccn + 1];
            float2 o0 = make_float2(acc[mi][ni][0] + bx, acc[mi][ni][1] + by);
            float2 o1 = make_float2(acc[mi][ni][2] + bx, acc[mi][ni][3] + by);
            *(float2*)&C[(size_t)rr * N + ccn]       = o0;
            *(float2*)&C[(size_t)(rr + 8) * N + ccn] = o1;
        }
    }
}

// ---------------------------------------------------------------------------
// Tensor-core flash attention.
// Block = 128 threads (4 warps), q-tile 64 (16 rows per warp), k-chunks of 64.
// QK^T: f16 3-term hi/lo mma (error ~2^-22).
// softmax: ex2.approx.f16x2 -> P directly in f16 A-fragment layout.
// PV: f16 2-term (p*vh + p*vl); row-sum l via "ones" column of V (O tile 8).
// Output written as bf16 hi/lo for the projection GEMM.
// ---------------------------------------------------------------------------
__global__ __launch_bounds__(128) void attn_mma_kernel(
    const __half* __restrict__ qh_g, const __half* __restrict__ ql_g,
    const __half* __restrict__ kh_g, const __half* __restrict__ kl_g,
    const __half* __restrict__ vh_g, const __half* __restrict__ vl_g,
    __nv_bfloat16* __restrict__ oh, __nv_bfloat16* __restrict__ ol)
{
    __shared__ __align__(16) __half sK[2][64][72];   // hi, lo
    __shared__ __align__(16) __half sV[2][64][88];   // hi, lo (+ones col 64)

    const int tid  = threadIdx.x;
    const int wid  = tid >> 5;
    const int lane = tid & 31;
    const int g  = lane >> 2;
    const int cq = lane & 3;
    const int qt = blockIdx.x;
    const int h  = blockIdx.y;
    const int b  = blockIdx.z;
    const int q0 = qt * 64;
    const float cE = 0.125f * 1.44269504089f;   // scale * log2(e)

    const uint32_t sKhiB = smem_u32(sK);
    const uint32_t sKloB = sKhiB + 64 * 72 * 2;
    const uint32_t sVhiB = smem_u32(sV);
    const uint32_t sVloB = sVhiB + 64 * 88 * 2;

    // ones column of V-hi (col 64), zeros 65..71; never clobbered by cp.async
    if (tid < 64) {
        #pragma unroll
        for (int j = 0; j < 8; j++) {
            sV[0][tid][64 + j] = (j == 0) ? __float2half(1.f) : __float2half(0.f);
            sV[1][tid][64 + j] = __float2half(0.f);
        }
    }

    // ---- stage Q (hi/lo) into the K smem area, load fragments to registers
    {
        const __half* qh_p = qh_g + (size_t)(b * T_ + q0) * C_ + h * HD_;
        const __half* ql_p = ql_g + (size_t)(b * T_ + q0) * C_ + h * HD_;
        #pragma unroll
        for (int i = 0; i < 4; i++) {
            int idx = i * 128 + tid;
            int row = idx >> 3, c16 = idx & 7;
            size_t go = (size_t)row * C_ + c16 * 8;
            uint32_t so = (uint32_t)((row * 72 + c16 * 8) * 2);
            cp_async16(sKhiB + so, qh_p + go);
            cp_async16(sKloB + so, ql_p + go);
        }
        cp_commit();
        cp_wait<0>();
        __syncthreads();
    }
    uint32_t qh[4][4], ql[4][4];
    const int a_r = lane & 15;
    const int a_k = (lane >> 4) * 8;
    #pragma unroll
    for (int hs = 0; hs < 4; hs++) {
        uint32_t off = (uint32_t)(((wid * 16 + a_r) * 72 + hs * 16 + a_k) * 2);
        ldm_x4(qh[hs], sKhiB + off);
        ldm_x4(ql[hs], sKloB + off);
    }

    float o[9][4];
    #pragma unroll
    for (int t = 0; t < 9; t++)
        #pragma unroll
        for (int j = 0; j < 4; j++) o[t][j] = 0.f;
    float mi0 = -1e30f, mi1 = -1e30f;

    const int qg0 = q0 + wid * 16 + g;
    const int qg1 = qg0 + 8;
    const int vb_k = (lane & 7) + ((lane >> 3) & 1) * 8;
    const int vb_n = (lane >> 4) * 8;

    const int nkt = qt + 1;
    for (int kt = 0; kt < nkt; kt++) {
        __syncthreads();   // previous chunk's reads done before refill
        // ---- fill K,V tiles via cp.async (f16 hi/lo, pre-split)
        {
            const size_t gbase = (size_t)(b * T_ + kt * 64) * C_ + h * HD_;
            #pragma unroll
            for (int i = 0; i < 4; i++) {
                int idx = i * 128 + tid;
                int row = idx >> 3, c16 = idx & 7;
                size_t go = gbase + (size_t)row * C_ + c16 * 8;
                uint32_t so72 = (uint32_t)((row * 72 + c16 * 8) * 2);
                uint32_t so88 = (uint32_t)((row * 88 + c16 * 8) * 2);
                cp_async16(sKhiB + so72, kh_g + go);
                cp_async16(sKloB + so72, kl_g + go);
                cp_async16(sVhiB + so88, vh_g + go);
                cp_async16(sVloB + so88, vl_g + go);
            }
            cp_commit();
            cp_wait<0>();
            __syncthreads();
        }

        // ---- S = Q @ K^T  (f16 3-term)
        float s[8][4];
        #pragma unroll
        for (int t = 0; t < 8; t++)
            #pragma unroll
            for (int j = 0; j < 4; j++) s[t][j] = 0.f;

        #pragma unroll
        for (int hs = 0; hs < 4; hs++) {
            #pragma unroll
            for (int g16 = 0; g16 < 4; g16++) {
                uint32_t kh4[4], kl4[4];
                uint32_t off = (uint32_t)(((g16 * 16 + a_r) * 72 + hs * 16 + a_k) * 2);
                ldm_x4(kh4, sKhiB + off);
                ldm_x4(kl4, sKloB + off);
                uint32_t bh0[2] = {kh4[0], kh4[2]}, bh1[2] = {kh4[1], kh4[3]};
                uint32_t bl0[2] = {kl4[0], kl4[2]}, bl1[2] = {kl4[1], kl4[3]};
                const int t0 = 2 * g16, t1 = t0 + 1;
                mma_f16(s[t0], qh[hs], bh0);
                mma_f16(s[t0], qh[hs], bl0);
                mma_f16(s[t0], ql[hs], bh0);
                mma_f16(s[t1], qh[hs], bh1);
                mma_f16(s[t1], qh[hs], bl1);
                mma_f16(s[t1], ql[hs], bh1);
            }
        }

        // ---- causal mask (diagonal chunk only)
        if (kt == qt) {
            const int k0 = kt * 64;
            #pragma unroll
            for (int nt = 0; nt < 8; nt++) {
                const int kgb = k0 + nt * 8 + 2 * cq;
                if (kgb     > qg0) s[nt][0] = -1e30f;
                if (kgb + 1 > qg0) s[nt][1] = -1e30f;
                if (kgb     > qg1) s[nt][2] = -1e30f;
                if (kgb + 1 > qg1) s[nt][3] = -1e30f;
            }
        }

        // ---- online softmax (per-row over 4 lanes)
        float mx0 = mi0, mx1 = mi1;
        #pragma unroll
        for (int nt = 0; nt < 8; nt++) {
            mx0 = fmaxf(mx0, fmaxf(s[nt][0], s[nt][1]));
            mx1 = fmaxf(mx1, fmaxf(s[nt][2], s[nt][3]));
        }
        #pragma unroll
        for (int off = 1; off <= 2; off <<= 1) {
            mx0 = fmaxf(mx0, __shfl_xor_sync(0xffffffffu, mx0, off));
            mx1 = fmaxf(mx1, __shfl_xor_sync(0xffffffffu, mx1, off));
        }
        const float alpha0 = fex2((mi0 - mx0) * cE);
        const float alpha1 = fex2((mi1 - mx1) * cE);
        mi0 = mx0; mi1 = mx1;
        const float b0 = mx0 * cE, b1 = mx1 * cE;

        uint32_t ph[8][2];
        #pragma unroll
        for (int nt = 0; nt < 8; nt++) {
            float f0 = s[nt][0] * cE - b0;
            float f1 = s[nt][1] * cE - b0;
            float f2 = s[nt][2] * cE - b1;
            float f3 = s[nt][3] * cE - b1;
            ph[nt][0] = ex2_f16x2(cvt_f16x2(f1, f0));
            ph[nt][1] = ex2_f16x2(cvt_f16x2(f3, f2));
        }
        #pragma unroll
        for (int t = 0; t < 9; t++) {
            o[t][0] *= alpha0; o[t][1] *= alpha0;
            o[t][2] *= alpha1; o[t][3] *= alpha1;
        }

        // ---- O += P @ V  (f16 2-term) + l via ones column
        #pragma unroll
        for (int kb = 0; kb < 4; kb++) {
            uint32_t ap[4] = { ph[2 * kb][0], ph[2 * kb][1],
                               ph[2 * kb + 1][0], ph[2 * kb + 1][1] };
            #pragma unroll
            for (int ng = 0; ng < 4; ng++) {
                uint32_t vh4[4], vl4[4];
                uint32_t off = (uint32_t)(((kb * 16 + vb_k) * 88 + ng * 16 + vb_n) * 2);
                ldm_x4_t(vh4, sVhiB + off);
                ldm_x4_t(vl4, sVloB + off);
                uint32_t vh0[2] = {vh4[0], vh4[1]}, vh1[2] = {vh4[2], vh4[3]};
                uint32_t vl0[2] = {vl4[0], vl4[1]}, vl1[2] = {vl4[2], vl4[3]};
                mma_f16(o[2 * ng],     ap, vh0);
                mma_f16(o[2 * ng],     ap, vl0);
                mma_f16(o[2 * ng + 1], ap, vh1);
                mma_f16(o[2 * ng + 1], ap, vl1);
            }
            uint32_t vo[2];
            uint32_t off1 = (uint32_t)(((kb * 16 + vb_k) * 88 + 64) * 2);
            ldm_x2_t(vo, sVhiB + off1);
            mma_f16(o[8], ap, vo);
        }
    }

    // ---- epilogue: normalize by l (O tile 8, col 64 lives at lanes with cq==0)
    const float l0 = __shfl_sync(0xffffffffu, o[8][0], lane & 28);
    const float l1 = __shfl_sync(0xffffffffu, o[8][2], lane & 28);
    const float i0 = 1.f / l0;
    const float i1 = 1.f / l1;
    const size_t r0 = (size_t)(b * T_ + q0 + wid * 16 + g);
    #pragma unroll
    for (int nt = 0; nt < 8; nt++) {
        const int cc = h * HD_ + nt * 8 + 2 * cq;
        float x0 = o[nt][0] * i0, x1 = o[nt][1] * i0;
        float y0 = o[nt][2] * i1, y1 = o[nt][3] * i1;
        float hx0 = __bfloat162float(__float2bfloat16(x0));
        float hx1 = __bfloat162float(__float2bfloat16(x1));
        float hy0 = __bfloat162float(__float2bfloat16(y0));
        float hy1 = __bfloat162float(__float2bfloat16(y1));
        *(uint32_t*)&oh[r0 * C_ + cc]       = pack_bf16(x0, x1);
        *(uint32_t*)&ol[r0 * C_ + cc]       = pack_bf16(x0 - hx0, x1 - hx1);
        *(uint32_t*)&oh[(r0 + 8) * C_ + cc] = pack_bf16(y0, y1);
        *(uint32_t*)&ol[(r0 + 8) * C_ + cc] = pack_bf16(y0 - hy0, y1 - hy1);
    }
}

// ---------------------------------------------------------------------------
extern "C" void kernel_launch(void* const* d_in, const int* in_sizes, int n_in,
                              void* d_out, int out_size)
{
    const float* x     = (const float*)d_in[0];
    const float* Wqkv  = (const float*)d_in[1];
    const float* bqkv  = (const float*)d_in[2];
    const float* Wproj = (const float*)d_in[3];
    const float* bproj = (const float*)d_in[4];
    float* out = (float*)d_out;

    float* qkv = nullptr;
    __nv_bfloat16 *xh, *xl, *wqh, *wql, *wph, *wpl, *ah, *al;
    __half *fqh, *fql, *fkh, *fkl, *fvh, *fvl;
    cudaGetSymbolAddress((void**)&qkv, g_qkv);
    cudaGetSymbolAddress((void**)&xh,  g_xh);
    cudaGetSymbolAddress((void**)&xl,  g_xl);
    cudaGetSymbolAddress((void**)&wqh, g_wqh);
    cudaGetSymbolAddress((void**)&wql, g_wql);
    cudaGetSymbolAddress((void**)&wph, g_wph);
    cudaGetSymbolAddress((void**)&wpl, g_wpl);
    cudaGetSymbolAddress((void**)&ah,  g_ah);
    cudaGetSymbolAddress((void**)&al,  g_al);
    cudaGetSymbolAddress((void**)&fqh, g_fqh);
    cudaGetSymbolAddress((void**)&fql, g_fql);
    cudaGetSymbolAddress((void**)&fkh, g_fkh);
    cudaGetSymbolAddress((void**)&fkl, g_fkl);
    cudaGetSymbolAddress((void**)&fvh, g_fvh);
    cudaGetSymbolAddress((void**)&fvl, g_fvl);

    // 0) split GEMM inputs into bf16 hi/lo
    split_kernel<<<(MR_ * C_) / 1024, 256>>>(x, xh, xl, MR_ * C_);
    split_kernel<<<(C_ * C3_) / 1024, 256>>>(Wqkv, wqh, wql, C_ * C3_);
    split_kernel<<<(C_ * C_) / 1024, 256>>>(Wproj, wph, wpl, C_ * C_);

    // 1) qkv = x @ Wqkv + bqkv   [4096, 2304]
    gemm_bf16x3_kernel<<<dim3(C3_ / 128, MR_ / 128), 256>>>(
        xh, xl, wqh, wql, bqkv, qkv, MR_, C3_, C_);

    // 2) split q/k/v into f16 hi/lo for tensor-core attention
    split_qkv_kernel<<<(MR_ * C3_) / 1024, 256>>>(qkv, fqh, fql, fkh, fkl, fvh, fvl);

    // 3) tensor-core flash attention -> bf16 hi/lo [4096, 768]
    attn_mma_kernel<<<dim3(T_ / 64, NH_, B_), 128>>>(
        fqh, fql, fkh, fkl, fvh, fvl, ah, al);

    // 4) out = attn @ Wproj + bproj   [4096, 768]
    gemm_bf16x3_kernel<<<dim3(C_ / 128, MR_ / 128), 256>>>(
        ah, al, wph, wpl, bproj, out, MR_, C_, C_);
}